// round 3
// baseline (speedup 1.0000x reference)
#include <cuda_runtime.h>
#include <cuda_bf16.h>
#include <math.h>
#include <stdint.h>

// Problem constants
#define BB 32
#define LQ 256
#define LK 512
#define HH 256
#define NHD 8
#define DH 32
#define NN 8192
#define H2 512          // 2*H
#define INV_SQRT_DH 0.17677669529663687f

// ---------------- device scratch (allocation-free rule: device globals) ----------
__device__ float g_key_pad[BB * LK * H2];        // 8.4M
__device__ float g_val_pad[BB * LK * HH];        // 4.2M
__device__ float g_Q[BB * LQ * HH];              // 2.1M
__device__ float g_K[BB * LK * HH];              // 4.2M
__device__ float g_V[BB * LK * HH];              // 4.2M
__device__ float g_scores[BB * NHD * LQ * LK];   // 33.6M
__device__ float g_pq[BB * NHD * LQ * LK];       // 33.6M
__device__ float g_pvT[BB * NHD * LQ * LK];      // 33.6M  (layout [bh][q][k])
__device__ float g_qctx[BB * LQ * HH];
__device__ float g_vctx[BB * LK * HH];
__device__ float g_O[BB * LQ * HH];
__device__ float g_T1[BB * LK * HH];
__device__ float g_T2[BB * LK * HH];
__device__ float g_vnew[BB * LK * HH];
__device__ float g_sums[NN * HH];
__device__ float g_cnts[NN];

// ---------------- utility reductions (blockDim == 256) ---------------------------
__device__ __forceinline__ float block_reduce_sum(float v) {
    __shared__ float sh[8];
    #pragma unroll
    for (int o = 16; o > 0; o >>= 1) v += __shfl_down_sync(0xffffffffu, v, o);
    if ((threadIdx.x & 31) == 0) sh[threadIdx.x >> 5] = v;
    __syncthreads();
    if (threadIdx.x < 32) {
        float r = (threadIdx.x < 8) ? sh[threadIdx.x] : 0.0f;
        #pragma unroll
        for (int o = 4; o > 0; o >>= 1) r += __shfl_down_sync(0xffffffffu, r, o);
        if (threadIdx.x == 0) sh[0] = r;
    }
    __syncthreads();
    float r = sh[0];
    __syncthreads();
    return r;
}

__device__ __forceinline__ float block_reduce_max(float v) {
    __shared__ float shm[8];
    #pragma unroll
    for (int o = 16; o > 0; o >>= 1) v = fmaxf(v, __shfl_down_sync(0xffffffffu, v, o));
    if ((threadIdx.x & 31) == 0) shm[threadIdx.x >> 5] = v;
    __syncthreads();
    if (threadIdx.x < 32) {
        float r = (threadIdx.x < 8) ? shm[threadIdx.x] : -INFINITY;
        #pragma unroll
        for (int o = 4; o > 0; o >>= 1) r = fmaxf(r, __shfl_down_sync(0xffffffffu, r, o));
        if (threadIdx.x == 0) shm[0] = r;
    }
    __syncthreads();
    float r = shm[0];
    __syncthreads();
    return r;
}

// ---------------- zero fill ------------------------------------------------------
__global__ void zero_kernel(float* p, size_t n) {
    size_t i = (size_t)blockIdx.x * blockDim.x + threadIdx.x;
    size_t stride = (size_t)gridDim.x * blockDim.x;
    for (; i < n; i += stride) p[i] = 0.0f;
}

// ---------------- edge scatter (pad) ---------------------------------------------
__global__ void scatter_edges_kernel(const float* __restrict__ graph,
                                     const float* __restrict__ rel,
                                     const int* __restrict__ src, const int* __restrict__ dst,
                                     const int* __restrict__ eb, const int* __restrict__ ep,
                                     float* __restrict__ key_pad, float* __restrict__ val_pad) {
    int e = blockIdx.x;
    int t = threadIdx.x;
    int b = eb[e], p = ep[e], s = src[e], d = dst[e];
    size_t kbase = ((size_t)b * LK + p) * H2;
    key_pad[kbase + t]       = graph[(size_t)s * HH + t];
    key_pad[kbase + HH + t]  = rel[(size_t)e * HH + t];
    val_pad[((size_t)b * LK + p) * HH + t] = graph[(size_t)d * HH + t];
}

// ---------------- generic GEMM: C[M,N] = A[M,K] @ B[K,N] + bias ------------------
// BM=BN=64, BK=16, 256 threads, 4x4 per-thread micro tile
__global__ void gemm_bias_kernel(const float* __restrict__ A, const float* __restrict__ B,
                                 const float* __restrict__ bias, float* __restrict__ C,
                                 int M, int N, int K) {
    __shared__ float As[16][68];
    __shared__ float Bs[16][68];
    int tx = threadIdx.x & 15, ty = threadIdx.x >> 4;
    int m0 = blockIdx.y * 64, n0 = blockIdx.x * 64;
    float acc[4][4] = {};
    for (int k0 = 0; k0 < K; k0 += 16) {
        {   // A tile 64x16 -> As[k][m] (transposed)
            int row = threadIdx.x >> 2;
            int c4 = (threadIdx.x & 3) * 4;
            float4 v = *reinterpret_cast<const float4*>(&A[(size_t)(m0 + row) * K + k0 + c4]);
            As[c4 + 0][row] = v.x; As[c4 + 1][row] = v.y;
            As[c4 + 2][row] = v.z; As[c4 + 3][row] = v.w;
        }
        {   // B tile 16x64 -> Bs[k][n]
            int row = threadIdx.x >> 4;
            int c4 = (threadIdx.x & 15) * 4;
            float4 v = *reinterpret_cast<const float4*>(&B[(size_t)(k0 + row) * N + n0 + c4]);
            *reinterpret_cast<float4*>(&Bs[row][c4]) = v;
        }
        __syncthreads();
        #pragma unroll
        for (int kk = 0; kk < 16; kk++) {
            float4 a = *reinterpret_cast<const float4*>(&As[kk][ty * 4]);
            float4 b = *reinterpret_cast<const float4*>(&Bs[kk][tx * 4]);
            float av[4] = {a.x, a.y, a.z, a.w};
            float bv[4] = {b.x, b.y, b.z, b.w};
            #pragma unroll
            for (int i = 0; i < 4; i++)
                #pragma unroll
                for (int j = 0; j < 4; j++)
                    acc[i][j] += av[i] * bv[j];
        }
        __syncthreads();
    }
    #pragma unroll
    for (int i = 0; i < 4; i++)
        #pragma unroll
        for (int j = 0; j < 4; j++)
            C[(size_t)(m0 + ty * 4 + i) * N + n0 + tx * 4 + j] = acc[i][j] + bias[n0 + tx * 4 + j];
}

// ---------------- attention scores: S[bh][q][k] = Q.K^T * inv_sqrt(DH) -----------
// grid (LK/64, LQ/64, B*NH), block 256
__global__ void scores_kernel(const float* __restrict__ Q, const float* __restrict__ Kb,
                              float* __restrict__ S) {
    __shared__ float Qs[32][68];
    __shared__ float Ks[32][68];
    int bh = blockIdx.z;
    int b = bh >> 3, h = bh & 7;
    int q0 = blockIdx.y * 64, k0 = blockIdx.x * 64;
    const float* Qp = Q + (size_t)b * LQ * HH + h * DH;
    const float* Kp = Kb + (size_t)b * LK * HH + h * DH;
    int tx = threadIdx.x & 15, ty = threadIdx.x >> 4;
    #pragma unroll
    for (int it = 0; it < 2; it++) {
        int idx = it * 256 + threadIdx.x;
        int row = idx >> 3;
        int c4 = (idx & 7) * 4;
        float4 v = *reinterpret_cast<const float4*>(&Qp[(size_t)(q0 + row) * HH + c4]);
        Qs[c4 + 0][row] = v.x; Qs[c4 + 1][row] = v.y; Qs[c4 + 2][row] = v.z; Qs[c4 + 3][row] = v.w;
        float4 w = *reinterpret_cast<const float4*>(&Kp[(size_t)(k0 + row) * HH + c4]);
        Ks[c4 + 0][row] = w.x; Ks[c4 + 1][row] = w.y; Ks[c4 + 2][row] = w.z; Ks[c4 + 3][row] = w.w;
    }
    __syncthreads();
    float acc[4][4] = {};
    #pragma unroll
    for (int d = 0; d < 32; d++) {
        float4 a = *reinterpret_cast<const float4*>(&Qs[d][ty * 4]);
        float4 bq = *reinterpret_cast<const float4*>(&Ks[d][tx * 4]);
        float av[4] = {a.x, a.y, a.z, a.w};
        float bv[4] = {bq.x, bq.y, bq.z, bq.w};
        #pragma unroll
        for (int i = 0; i < 4; i++)
            #pragma unroll
            for (int j = 0; j < 4; j++)
                acc[i][j] += av[i] * bv[j];
    }
    #pragma unroll
    for (int i = 0; i < 4; i++)
        #pragma unroll
        for (int j = 0; j < 4; j++)
            S[((size_t)bh * LQ + q0 + ty * 4 + i) * LK + k0 + tx * 4 + j] = acc[i][j] * INV_SQRT_DH;
}

// ---------------- pq softmax over k (with padding mask) --------------------------
// grid = B*NH*LQ, block 256
__global__ void softmax_pq_kernel(const float* __restrict__ S, const float* __restrict__ pad_mask,
                                  float* __restrict__ P) {
    int gid = blockIdx.x;                // bh*LQ + q
    int bh = gid >> 8;
    int b = bh >> 3;
    const float* row = S + (size_t)gid * LK;
    int t = threadIdx.x;
    float v0 = row[t]       + (1.0f - pad_mask[b * LK + t])       * (-10000.0f);
    float v1 = row[t + 256] + (1.0f - pad_mask[b * LK + t + 256]) * (-10000.0f);
    float m = block_reduce_max(fmaxf(v0, v1));
    float e0 = expf(v0 - m), e1 = expf(v1 - m);
    float s = block_reduce_sum(e0 + e1);
    float inv = 1.0f / s;
    P[(size_t)gid * LK + t] = e0 * inv;
    P[(size_t)gid * LK + t + 256] = e1 * inv;
}

// ---------------- pv softmax over q, written transposed as pvT[bh][q][k] --------
// grid (LK/32, B*NH), block (32,8)
__global__ void softmax_pv_kernel(const float* __restrict__ S, const float* __restrict__ ext_mask,
                                  float* __restrict__ PT) {
    __shared__ float tile[256][33];
    __shared__ float red[8][32];
    __shared__ float colmax[32];
    __shared__ float colsum[32];
    int bh = blockIdx.y;
    int b = bh >> 3;
    int k0 = blockIdx.x * 32;
    int tx = threadIdx.x, ty = threadIdx.y;
    const float* Sp = S + (size_t)bh * LQ * LK;
    #pragma unroll 4
    for (int qq = 0; qq < 32; qq++) {
        int q = ty * 32 + qq;
        tile[q][tx] = Sp[(size_t)q * LK + k0 + tx] + ext_mask[b * LQ + q];
    }
    __syncthreads();
    float m = -INFINITY;
    #pragma unroll 4
    for (int qq = 0; qq < 32; qq++) m = fmaxf(m, tile[ty * 32 + qq][tx]);
    red[ty][tx] = m;
    __syncthreads();
    if (ty == 0) {
        float mm = red[0][tx];
        #pragma unroll
        for (int r = 1; r < 8; r++) mm = fmaxf(mm, red[r][tx]);
        colmax[tx] = mm;
    }
    __syncthreads();
    float cm = colmax[tx];
    float s = 0.0f;
    #pragma unroll 4
    for (int qq = 0; qq < 32; qq++) s += expf(tile[ty * 32 + qq][tx] - cm);
    red[ty][tx] = s;
    __syncthreads();
    if (ty == 0) {
        float ss = red[0][tx];
        #pragma unroll
        for (int r = 1; r < 8; r++) ss += red[r][tx];
        colsum[tx] = ss;
    }
    __syncthreads();
    float inv = 1.0f / colsum[tx];
    #pragma unroll 4
    for (int qq = 0; qq < 32; qq++) {
        int q = ty * 32 + qq;
        PT[((size_t)bh * LQ + q) * LK + k0 + tx] = expf(tile[q][tx] - cm) * inv;
    }
}

// ---------------- query_ctx[b,q,h*32+d] = sum_k pq[bh,q,k] * V[b,k,h*32+d] -------
// grid (LQ/128, B*NH), block 256; per-thread 8 rows x 2 cols
__global__ void qctx_kernel(const float* __restrict__ P, const float* __restrict__ V,
                            float* __restrict__ C) {
    __shared__ float Aq[128][36];
    __shared__ float Vs[32][36];
    int bh = blockIdx.y;
    int b = bh >> 3, h = bh & 7;
    int q0 = blockIdx.x * 128;
    int t = threadIdx.x;
    int d0 = (t & 15) * 2;
    int r0 = (t >> 4) * 8;
    const float* Pp = P + ((size_t)bh * LQ + q0) * LK;
    const float* Vp = V + (size_t)b * LK * HH + h * DH;
    float acc[8][2] = {};
    for (int kc = 0; kc < LK; kc += 32) {
        #pragma unroll
        for (int it = 0; it < 4; it++) {    // Aq: 128 rows x 32 k
            int idx = it * 256 + t;
            int row = idx >> 3;
            int c4 = (idx & 7) * 4;
            float4 v = *reinterpret_cast<const float4*>(&Pp[(size_t)row * LK + kc + c4]);
            *reinterpret_cast<float4*>(&Aq[row][c4]) = v;
        }
        {   // Vs: 32 k x 32 d
            int row = t >> 3;
            int c4 = (t & 7) * 4;
            float4 v = *reinterpret_cast<const float4*>(&Vp[(size_t)(kc + row) * HH + c4]);
            *reinterpret_cast<float4*>(&Vs[row][c4]) = v;
        }
        __syncthreads();
        #pragma unroll
        for (int kk = 0; kk < 32; kk++) {
            float b0 = Vs[kk][d0];
            float b1 = Vs[kk][d0 + 1];
            #pragma unroll
            for (int i = 0; i < 8; i++) {
                float a = Aq[r0 + i][kk];
                acc[i][0] += a * b0;
                acc[i][1] += a * b1;
            }
        }
        __syncthreads();
    }
    #pragma unroll
    for (int i = 0; i < 8; i++) {
        size_t o = ((size_t)b * LQ + q0 + r0 + i) * HH + h * DH + d0;
        C[o] = acc[i][0];
        C[o + 1] = acc[i][1];
    }
}

// ---------------- value_ctx[b,k,h*32+d] = sum_q pvT[bh,q,k] * Q[b,q,h*32+d] ------
// grid (LK/128, B*NH), block 256; per-thread 8 k-rows x 2 cols
__global__ void vctx_kernel(const float* __restrict__ PT, const float* __restrict__ Qb,
                            float* __restrict__ C) {
    __shared__ float Ps[32][132];
    __shared__ float Qs[32][36];
    int bh = blockIdx.y;
    int b = bh >> 3, h = bh & 7;
    int k0 = blockIdx.x * 128;
    int t = threadIdx.x;
    int d0 = (t & 15) * 2;
    int r0 = (t >> 4) * 8;
    const float* Pp = PT + (size_t)bh * LQ * LK + k0;
    const float* Qp = Qb + (size_t)b * LQ * HH + h * DH;
    float acc[8][2] = {};
    for (int qc = 0; qc < LQ; qc += 32) {
        #pragma unroll
        for (int it = 0; it < 4; it++) {    // Ps: 32 q x 128 k
            int idx = it * 256 + t;
            int row = idx >> 5;
            int c4 = (idx & 31) * 4;
            float4 v = *reinterpret_cast<const float4*>(&Pp[(size_t)(qc + row) * LK + c4]);
            *reinterpret_cast<float4*>(&Ps[row][c4]) = v;
        }
        {   // Qs: 32 q x 32 d
            int row = t >> 3;
            int c4 = (t & 7) * 4;
            float4 v = *reinterpret_cast<const float4*>(&Qp[(size_t)(qc + row) * HH + c4]);
            *reinterpret_cast<float4*>(&Qs[row][c4]) = v;
        }
        __syncthreads();
        #pragma unroll
        for (int qq = 0; qq < 32; qq++) {
            float b0 = Qs[qq][d0];
            float b1 = Qs[qq][d0 + 1];
            #pragma unroll
            for (int i = 0; i < 8; i++) {
                float a = Ps[qq][r0 + i];
                acc[i][0] += a * b0;
                acc[i][1] += a * b1;
            }
        }
        __syncthreads();
    }
    #pragma unroll
    for (int i = 0; i < 8; i++) {
        size_t o = ((size_t)b * LK + k0 + r0 + i) * HH + h * DH + d0;
        C[o] = acc[i][0];
        C[o + 1] = acc[i][1];
    }
}

// ---------------- query_out = LN(O + query) --------------------------------------
__global__ void ln_query_kernel(const float* __restrict__ O, const float* __restrict__ query,
                                const float* __restrict__ g, const float* __restrict__ bb,
                                float* __restrict__ out) {
    int row = blockIdx.x;
    int t = threadIdx.x;
    size_t i = (size_t)row * HH + t;
    float x = O[i] + query[i];
    float m = block_reduce_sum(x) * (1.0f / HH);
    float dx = x - m;
    float v = block_reduce_sum(dx * dx) * (1.0f / HH);
    out[i] = dx * rsqrtf(v + 1e-12f) * g[t] + bb[t];
}

// ---------------- value_new = LN(theta*vc + (1-theta)*vp) ------------------------
__global__ void gate_ln_kernel(const float* __restrict__ T1, const float* __restrict__ T2,
                               const float* __restrict__ VC, const float* __restrict__ VP,
                               const float* __restrict__ g, const float* __restrict__ bb,
                               float* __restrict__ vnew) {
    int row = blockIdx.x;
    int t = threadIdx.x;
    size_t i = (size_t)row * HH + t;
    float th = 1.0f / (1.0f + expf(-(T1[i] + T2[i])));
    float x = th * VC[i] + (1.0f - th) * VP[i];
    float m = block_reduce_sum(x) * (1.0f / HH);
    float dx = x - m;
    float v = block_reduce_sum(dx * dx) * (1.0f / HH);
    vnew[i] = dx * rsqrtf(v + 1e-12f) * g[t] + bb[t];
}

// ---------------- scatter mean ---------------------------------------------------
__global__ void scatter_sum_kernel(const float* __restrict__ vnew, const int* __restrict__ dst,
                                   const int* __restrict__ eb, const int* __restrict__ ep,
                                   float* __restrict__ sums, float* __restrict__ cnts) {
    int e = blockIdx.x;
    int t = threadIdx.x;
    int b = eb[e], p = ep[e], d = dst[e];
    atomicAdd(&sums[(size_t)d * HH + t], vnew[((size_t)b * LK + p) * HH + t]);
    if (t == 0) atomicAdd(&cnts[d], 1.0f);
}

__global__ void finalize_kernel(const float* __restrict__ sums, const float* __restrict__ cnts,
                                const float* __restrict__ graph, float* __restrict__ out) {
    size_t idx = (size_t)blockIdx.x * 256 + threadIdx.x;
    float c = cnts[idx >> 8];
    out[idx] = (c > 0.5f) ? sums[idx] / c : graph[idx];
}

// ---------------- host orchestration ---------------------------------------------
extern "C" void kernel_launch(void* const* d_in, const int* in_sizes, int n_in,
                              void* d_out, int out_size) {
    const float* ext   = (const float*)d_in[0];
    const float* query = (const float*)d_in[1];
    const float* rel   = (const float*)d_in[2];
    const float* graph = (const float*)d_in[3];
    const int*   src   = (const int*)d_in[4];
    const int*   dst   = (const int*)d_in[5];
    const int*   eb    = (const int*)d_in[6];
    const int*   ep    = (const int*)d_in[7];
    const float* pad   = (const float*)d_in[8];
    const float* Wq = (const float*)d_in[9];  const float* bq = (const float*)d_in[10];
    const float* Wk = (const float*)d_in[11]; const float* bk = (const float*)d_in[12];
    const float* Wv = (const float*)d_in[13]; const float* bv = (const float*)d_in[14];
    const float* Wo = (const float*)d_in[15]; const float* bo = (const float*)d_in[16];
    const float* l1g = (const float*)d_in[17]; const float* l1b = (const float*)d_in[18];
    const float* W1 = (const float*)d_in[19]; const float* b1 = (const float*)d_in[20];
    const float* W2 = (const float*)d_in[21]; const float* b2 = (const float*)d_in[22];
    const float* l2g = (const float*)d_in[23]; const float* l2b = (const float*)d_in[24];
    int E = in_sizes[4];
    float* out = (float*)d_out;

    float *kp, *vp, *Qb, *Kb, *Vb, *Sb, *Pq, *Pv, *qc, *vc, *Ob, *T1, *T2, *vn, *sums, *cnts;
    cudaGetSymbolAddress((void**)&kp, g_key_pad);
    cudaGetSymbolAddress((void**)&vp, g_val_pad);
    cudaGetSymbolAddress((void**)&Qb, g_Q);
    cudaGetSymbolAddress((void**)&Kb, g_K);
    cudaGetSymbolAddress((void**)&Vb, g_V);
    cudaGetSymbolAddress((void**)&Sb, g_scores);
    cudaGetSymbolAddress((void**)&Pq, g_pq);
    cudaGetSymbolAddress((void**)&Pv, g_pvT);
    cudaGetSymbolAddress((void**)&qc, g_qctx);
    cudaGetSymbolAddress((void**)&vc, g_vctx);
    cudaGetSymbolAddress((void**)&Ob, g_O);
    cudaGetSymbolAddress((void**)&T1, g_T1);
    cudaGetSymbolAddress((void**)&T2, g_T2);
    cudaGetSymbolAddress((void**)&vn, g_vnew);
    cudaGetSymbolAddress((void**)&sums, g_sums);
    cudaGetSymbolAddress((void**)&cnts, g_cnts);

    // 1. zero pads + accumulators
    zero_kernel<<<2048, 256>>>(kp, (size_t)BB * LK * H2);
    zero_kernel<<<2048, 256>>>(vp, (size_t)BB * LK * HH);
    zero_kernel<<<1024, 256>>>(sums, (size_t)NN * HH);
    zero_kernel<<<32, 256>>>(cnts, (size_t)NN);

    // 2. scatter edges into padded K/V inputs
    scatter_edges_kernel<<<E, 256>>>(graph, rel, src, dst, eb, ep, kp, vp);

    // 3. projections
    gemm_bias_kernel<<<dim3(4, 128), 256>>>(query, Wq, bq, Qb, BB * LQ, HH, HH);
    gemm_bias_kernel<<<dim3(4, 256), 256>>>(kp, Wk, bk, Kb, BB * LK, HH, H2);
    gemm_bias_kernel<<<dim3(4, 256), 256>>>(vp, Wv, bv, Vb, BB * LK, HH, HH);

    // 4. attention scores (shared by both softmaxes)
    scores_kernel<<<dim3(8, 4, BB * NHD), 256>>>(Qb, Kb, Sb);

    // 5. softmaxes
    softmax_pq_kernel<<<BB * NHD * LQ, 256>>>(Sb, pad, Pq);
    softmax_pv_kernel<<<dim3(16, BB * NHD), dim3(32, 8)>>>(Sb, ext, Pv);

    // 6. contexts
    qctx_kernel<<<dim3(2, BB * NHD), 256>>>(Pq, Vb, qc);
    vctx_kernel<<<dim3(4, BB * NHD), 256>>>(Pv, Qb, vc);

    // 7. output projection + LN (query_out -> second half of d_out)
    gemm_bias_kernel<<<dim3(4, 128), 256>>>(qc, Wo, bo, Ob, BB * LQ, HH, HH);
    ln_query_kernel<<<BB * LQ, 256>>>(Ob, query, l1g, l1b, out + (size_t)NN * HH);

    // 8. gate + LN
    gemm_bias_kernel<<<dim3(4, 256), 256>>>(vc, W1, b1, T1, BB * LK, HH, HH);
    gemm_bias_kernel<<<dim3(4, 256), 256>>>(vp, W2, b2, T2, BB * LK, HH, HH);
    gate_ln_kernel<<<BB * LK, 256>>>(T1, T2, vc, vp, l2g, l2b, vn);

    // 9. scatter-mean memory update (graph_new -> first half of d_out)
    scatter_sum_kernel<<<E, 256>>>(vn, dst, eb, ep, sums, cnts);
    finalize_kernel<<<NN, 256>>>(sums, cnts, graph, out);
}

// round 5
// speedup vs baseline: 1.3997x; 1.3997x over previous
#include <cuda_runtime.h>
#include <cuda_bf16.h>
#include <math.h>
#include <stdint.h>

// Problem constants
#define BB 32
#define LQ 256
#define LK 512
#define HH 256
#define NHD 8
#define DH 32
#define NN 8192
#define H2 512          // 2*H
#define INV_SQRT_DH 0.17677669529663687f

// ---------------- device scratch (allocation-free rule: device globals) ----------
__device__ float g_key_pad[BB * LK * H2];
__device__ float g_val_pad[BB * LK * HH];
__device__ float g_Q[BB * LQ * HH];
__device__ float g_K[BB * LK * HH];
__device__ float g_V[BB * LK * HH];
__device__ float g_scores[BB * NHD * LQ * LK];   // [bh][q][k]
__device__ float g_pq[BB * NHD * LQ * LK];       // [bh][q][k]
__device__ float g_pv[BB * NHD * LK * LQ];       // [bh][k][q]  (k-major!)
__device__ float g_qctx[BB * LQ * HH];
__device__ float g_vctx[BB * LK * HH];
__device__ float g_O[BB * LQ * HH];
__device__ float g_T1[BB * LK * HH];
__device__ float g_T2[BB * LK * HH];
__device__ float g_vnew[BB * LK * HH];
__device__ float g_sums[NN * HH];
__device__ float g_cnts[NN];

// ---------------- tf32 helpers ---------------------------------------------------
__device__ __forceinline__ float to_tf32(float x) {
    asm("cvt.rna.tf32.f32 %0, %0;" : "+f"(x));
    return x;
}

__device__ __forceinline__ void mma_tf32(float* d, const uint32_t* a, const uint32_t* b) {
    asm volatile("mma.sync.aligned.m16n8k8.row.col.f32.tf32.tf32.f32 "
                 "{%0,%1,%2,%3},{%4,%5,%6,%7},{%8,%9},{%0,%1,%2,%3};\n"
                 : "+f"(d[0]), "+f"(d[1]), "+f"(d[2]), "+f"(d[3])
                 : "r"(a[0]), "r"(a[1]), "r"(a[2]), "r"(a[3]),
                   "r"(b[0]), "r"(b[1]));
}

// ---------------- utility reductions (blockDim == 256) ---------------------------
__device__ __forceinline__ float block_reduce_sum(float v) {
    __shared__ float sh[8];
    #pragma unroll
    for (int o = 16; o > 0; o >>= 1) v += __shfl_down_sync(0xffffffffu, v, o);
    if ((threadIdx.x & 31) == 0) sh[threadIdx.x >> 5] = v;
    __syncthreads();
    if (threadIdx.x < 32) {
        float r = (threadIdx.x < 8) ? sh[threadIdx.x] : 0.0f;
        #pragma unroll
        for (int o = 4; o > 0; o >>= 1) r += __shfl_down_sync(0xffffffffu, r, o);
        if (threadIdx.x == 0) sh[0] = r;
    }
    __syncthreads();
    float r = sh[0];
    __syncthreads();
    return r;
}

__device__ __forceinline__ float block_reduce_max(float v) {
    __shared__ float shm[8];
    #pragma unroll
    for (int o = 16; o > 0; o >>= 1) v = fmaxf(v, __shfl_down_sync(0xffffffffu, v, o));
    if ((threadIdx.x & 31) == 0) shm[threadIdx.x >> 5] = v;
    __syncthreads();
    if (threadIdx.x < 32) {
        float r = (threadIdx.x < 8) ? shm[threadIdx.x] : -INFINITY;
        #pragma unroll
        for (int o = 4; o > 0; o >>= 1) r = fmaxf(r, __shfl_down_sync(0xffffffffu, r, o));
        if (threadIdx.x == 0) shm[0] = r;
    }
    __syncthreads();
    float r = shm[0];
    __syncthreads();
    return r;
}

// ---------------- zero fill ------------------------------------------------------
__global__ void zero_kernel(float* p, size_t n) {
    size_t i = (size_t)blockIdx.x * blockDim.x + threadIdx.x;
    size_t stride = (size_t)gridDim.x * blockDim.x;
    for (; i < n; i += stride) p[i] = 0.0f;
}

// ---------------- edge scatter (pad) ---------------------------------------------
__global__ void scatter_edges_kernel(const float* __restrict__ graph,
                                     const float* __restrict__ rel,
                                     const int* __restrict__ src, const int* __restrict__ dst,
                                     const int* __restrict__ eb, const int* __restrict__ ep,
                                     float* __restrict__ key_pad, float* __restrict__ val_pad) {
    int e = blockIdx.x;
    int t = threadIdx.x;
    int b = eb[e], p = ep[e], s = src[e], d = dst[e];
    size_t kbase = ((size_t)b * LK + p) * H2;
    key_pad[kbase + t]       = graph[(size_t)s * HH + t];
    key_pad[kbase + HH + t]  = rel[(size_t)e * HH + t];
    val_pad[((size_t)b * LK + p) * HH + t] = graph[(size_t)d * HH + t];
}

// ---------------- dense tf32 GEMM: C[M,N] = A[M,K]@B[K,N] + bias -----------------
// BM=128, BN=64, BK=32; 256 threads = 8 warps, warp grid 2(m) x 4(n)
// per warp: 4 m-tiles (16) x 2 n-tiles (8), mma m16n8k8
__global__ void gemm_tf32_kernel(const float* __restrict__ A, const float* __restrict__ B,
                                 const float* __restrict__ bias, float* __restrict__ C,
                                 int M, int N, int K) {
    __shared__ float As[32][136];   // [k][m]  (136%32==8 -> conflict-free frag reads)
    __shared__ float Bs[32][72];    // [k][n]  (72%32==8)
    int tid = threadIdx.x;
    int wid = tid >> 5, lane = tid & 31;
    int wm = wid >> 2, wn = wid & 3;
    int gr = lane >> 2, tg = lane & 3;
    int m0 = blockIdx.y * 128, n0 = blockIdx.x * 64;
    float acc[4][2][4] = {};
    for (int k0 = 0; k0 < K; k0 += 32) {
        {   // A tile 128x32 -> As[k][m] transposed
            int row = tid >> 1;
            int kb = (tid & 1) * 16;
            const float* ap = &A[(size_t)(m0 + row) * K + k0 + kb];
            #pragma unroll
            for (int j = 0; j < 16; j += 4) {
                float4 v = *reinterpret_cast<const float4*>(ap + j);
                As[kb + j + 0][row] = to_tf32(v.x);
                As[kb + j + 1][row] = to_tf32(v.y);
                As[kb + j + 2][row] = to_tf32(v.z);
                As[kb + j + 3][row] = to_tf32(v.w);
            }
        }
        {   // B tile 32x64 -> Bs[k][n]
            int row = tid >> 3;
            int cb = (tid & 7) * 8;
            const float* bp = &B[(size_t)(k0 + row) * N + n0 + cb];
            float4 v0 = *reinterpret_cast<const float4*>(bp);
            float4 v1 = *reinterpret_cast<const float4*>(bp + 4);
            Bs[row][cb + 0] = to_tf32(v0.x); Bs[row][cb + 1] = to_tf32(v0.y);
            Bs[row][cb + 2] = to_tf32(v0.z); Bs[row][cb + 3] = to_tf32(v0.w);
            Bs[row][cb + 4] = to_tf32(v1.x); Bs[row][cb + 5] = to_tf32(v1.y);
            Bs[row][cb + 6] = to_tf32(v1.z); Bs[row][cb + 7] = to_tf32(v1.w);
        }
        __syncthreads();
        #pragma unroll
        for (int ks = 0; ks < 4; ks++) {
            int kk = ks * 8;
            uint32_t af[4][4], bf[2][2];
            #pragma unroll
            for (int mt = 0; mt < 4; mt++) {
                int mr = wm * 64 + mt * 16 + gr;
                af[mt][0] = __float_as_uint(As[kk + tg][mr]);
                af[mt][1] = __float_as_uint(As[kk + tg][mr + 8]);
                af[mt][2] = __float_as_uint(As[kk + tg + 4][mr]);
                af[mt][3] = __float_as_uint(As[kk + tg + 4][mr + 8]);
            }
            #pragma unroll
            for (int nt = 0; nt < 2; nt++) {
                int nc = wn * 16 + nt * 8 + gr;
                bf[nt][0] = __float_as_uint(Bs[kk + tg][nc]);
                bf[nt][1] = __float_as_uint(Bs[kk + tg + 4][nc]);
            }
            #pragma unroll
            for (int mt = 0; mt < 4; mt++)
                #pragma unroll
                for (int nt = 0; nt < 2; nt++)
                    mma_tf32(acc[mt][nt], af[mt], bf[nt]);
        }
        __syncthreads();
    }
    #pragma unroll
    for (int mt = 0; mt < 4; mt++) {
        int r0 = m0 + wm * 64 + mt * 16 + gr;
        #pragma unroll
        for (int nt = 0; nt < 2; nt++) {
            int c = n0 + wn * 16 + nt * 8 + tg * 2;
            float b0v = bias[c], b1v = bias[c + 1];
            float2 v0 = {acc[mt][nt][0] + b0v, acc[mt][nt][1] + b1v};
            float2 v1 = {acc[mt][nt][2] + b0v, acc[mt][nt][3] + b1v};
            *reinterpret_cast<float2*>(&C[(size_t)r0 * N + c]) = v0;
            *reinterpret_cast<float2*>(&C[(size_t)(r0 + 8) * N + c]) = v1;
        }
    }
}

// ---------------- scores tf32: S[bh,q,k] = Qh[q,:] . Kh[k,:] * scale -------------
// grid (LK/64, LQ/128, B*NH), 256 threads, K = DH = 32 in one shot
__global__ void scores_tf32_kernel(const float* __restrict__ Q, const float* __restrict__ Kb,
                                   float* __restrict__ S) {
    __shared__ float As[32][136];   // [d][q]
    __shared__ float Ks[32][72];    // [d][k]
    int tid = threadIdx.x;
    int wid = tid >> 5, lane = tid & 31;
    int wm = wid >> 2, wn = wid & 3;
    int gr = lane >> 2, tg = lane & 3;
    int bh = blockIdx.z;
    int b = bh >> 3, h = bh & 7;
    int q0 = blockIdx.y * 128, k0 = blockIdx.x * 64;
    const float* Qp = Q + (size_t)b * LQ * HH + h * DH;
    const float* Kp = Kb + (size_t)b * LK * HH + h * DH;
    {   // Q tile 128x32 -> As[d][q]
        int row = tid >> 1;
        int kb = (tid & 1) * 16;
        const float* ap = &Qp[(size_t)(q0 + row) * HH + kb];
        #pragma unroll
        for (int j = 0; j < 16; j += 4) {
            float4 v = *reinterpret_cast<const float4*>(ap + j);
            As[kb + j + 0][row] = to_tf32(v.x);
            As[kb + j + 1][row] = to_tf32(v.y);
            As[kb + j + 2][row] = to_tf32(v.z);
            As[kb + j + 3][row] = to_tf32(v.w);
        }
    }
    {   // K tile 64x32 -> Ks[d][k] transposed
        int row = tid >> 2;
        int cb = (tid & 3) * 8;
        const float* bp = &Kp[(size_t)(k0 + row) * HH + cb];
        float4 v0 = *reinterpret_cast<const float4*>(bp);
        float4 v1 = *reinterpret_cast<const float4*>(bp + 4);
        Ks[cb + 0][row] = to_tf32(v0.x); Ks[cb + 1][row] = to_tf32(v0.y);
        Ks[cb + 2][row] = to_tf32(v0.z); Ks[cb + 3][row] = to_tf32(v0.w);
        Ks[cb + 4][row] = to_tf32(v1.x); Ks[cb + 5][row] = to_tf32(v1.y);
        Ks[cb + 6][row] = to_tf32(v1.z); Ks[cb + 7][row] = to_tf32(v1.w);
    }
    __syncthreads();
    float acc[4][2][4] = {};
    #pragma unroll
    for (int ks = 0; ks < 4; ks++) {
        int kk = ks * 8;
        uint32_t af[4][4], bf[2][2];
        #pragma unroll
        for (int mt = 0; mt < 4; mt++) {
            int mr = wm * 64 + mt * 16 + gr;
            af[mt][0] = __float_as_uint(As[kk + tg][mr]);
            af[mt][1] = __float_as_uint(As[kk + tg][mr + 8]);
            af[mt][2] = __float_as_uint(As[kk + tg + 4][mr]);
            af[mt][3] = __float_as_uint(As[kk + tg + 4][mr + 8]);
        }
        #pragma unroll
        for (int nt = 0; nt < 2; nt++) {
            int nc = wn * 16 + nt * 8 + gr;
            bf[nt][0] = __float_as_uint(Ks[kk + tg][nc]);
            bf[nt][1] = __float_as_uint(Ks[kk + tg + 4][nc]);
        }
        #pragma unroll
        for (int mt = 0; mt < 4; mt++)
            #pragma unroll
            for (int nt = 0; nt < 2; nt++)
                mma_tf32(acc[mt][nt], af[mt], bf[nt]);
    }
    #pragma unroll
    for (int mt = 0; mt < 4; mt++) {
        int r0 = q0 + wm * 64 + mt * 16 + gr;
        #pragma unroll
        for (int nt = 0; nt < 2; nt++) {
            int c = k0 + wn * 16 + nt * 8 + tg * 2;
            float2 v0 = {acc[mt][nt][0] * INV_SQRT_DH, acc[mt][nt][1] * INV_SQRT_DH};
            float2 v1 = {acc[mt][nt][2] * INV_SQRT_DH, acc[mt][nt][3] * INV_SQRT_DH};
            *reinterpret_cast<float2*>(&S[((size_t)bh * LQ + r0) * LK + c]) = v0;
            *reinterpret_cast<float2*>(&S[((size_t)bh * LQ + r0 + 8) * LK + c]) = v1;
        }
    }
}

// ---------------- batched ctx tf32: C[m, d] = sum_k A[m,k] * Bh[k,d] -------------
// A: [bh][M][Kd]; B head-sliced, row stride HH; C head-sliced, row stride HH
// BM=128, BN=32(=DH), BK=32; 8 warps: warp grid 4(m) x 2(n)
__global__ void ctx_tf32_kernel(const float* __restrict__ A, const float* __restrict__ B,
                                float* __restrict__ C, int M, int Kd) {
    __shared__ float As[32][136];   // [k][m]
    __shared__ float Bs[32][40];    // [k][n]
    int tid = threadIdx.x;
    int wid = tid >> 5, lane = tid & 31;
    int wm = wid >> 1, wn = wid & 1;
    int gr = lane >> 2, tg = lane & 3;
    int bh = blockIdx.y;
    int b = bh >> 3, h = bh & 7;
    int m0 = blockIdx.x * 128;
    const float* Ap = A + (size_t)bh * M * Kd;
    const float* Bp = B + (size_t)b * Kd * HH + h * DH;
    float* Cp = C + (size_t)b * M * HH + h * DH;
    float acc[2][2][4] = {};
    for (int k0 = 0; k0 < Kd; k0 += 32) {
        {   // A tile 128x32 -> As[k][m]
            int row = tid >> 1;
            int kb = (tid & 1) * 16;
            const float* ap = &Ap[(size_t)(m0 + row) * Kd + k0 + kb];
            #pragma unroll
            for (int j = 0; j < 16; j += 4) {
                float4 v = *reinterpret_cast<const float4*>(ap + j);
                As[kb + j + 0][row] = to_tf32(v.x);
                As[kb + j + 1][row] = to_tf32(v.y);
                As[kb + j + 2][row] = to_tf32(v.z);
                As[kb + j + 3][row] = to_tf32(v.w);
            }
        }
        {   // B tile 32x32 -> Bs[k][n]
            int row = tid >> 3;
            int cb = (tid & 7) * 4;
            float4 v = *reinterpret_cast<const float4*>(&Bp[(size_t)(k0 + row) * HH + cb]);
            Bs[row][cb + 0] = to_tf32(v.x); Bs[row][cb + 1] = to_tf32(v.y);
            Bs[row][cb + 2] = to_tf32(v.z); Bs[row][cb + 3] = to_tf32(v.w);
        }
        __syncthreads();
        #pragma unroll
        for (int ks = 0; ks < 4; ks++) {
            int kk = ks * 8;
            uint32_t af[2][4], bf[2][2];
            #pragma unroll
            for (int mt = 0; mt < 2; mt++) {
                int mr = wm * 32 + mt * 16 + gr;
                af[mt][0] = __float_as_uint(As[kk + tg][mr]);
                af[mt][1] = __float_as_uint(As[kk + tg][mr + 8]);
                af[mt][2] = __float_as_uint(As[kk + tg + 4][mr]);
                af[mt][3] = __float_as_uint(As[kk + tg + 4][mr + 8]);
            }
            #pragma unroll
            for (int nt = 0; nt < 2; nt++) {
                int nc = wn * 16 + nt * 8 + gr;
                bf[nt][0] = __float_as_uint(Bs[kk + tg][nc]);
                bf[nt][1] = __float_as_uint(Bs[kk + tg + 4][nc]);
            }
            #pragma unroll
            for (int mt = 0; mt < 2; mt++)
                #pragma unroll
                for (int nt = 0; nt < 2; nt++)
                    mma_tf32(acc[mt][nt], af[mt], bf[nt]);
        }
        __syncthreads();
    }
    #pragma unroll
    for (int mt = 0; mt < 2; mt++) {
        int r0 = m0 + wm * 32 + mt * 16 + gr;
        #pragma unroll
        for (int nt = 0; nt < 2; nt++) {
            int c = wn * 16 + nt * 8 + tg * 2;
            float2 v0 = {acc[mt][nt][0], acc[mt][nt][1]};
            float2 v1 = {acc[mt][nt][2], acc[mt][nt][3]};
            *reinterpret_cast<float2*>(&Cp[(size_t)r0 * HH + c]) = v0;
            *reinterpret_cast<float2*>(&Cp[(size_t)(r0 + 8) * HH + c]) = v1;
        }
    }
}

// ---------------- pq softmax over k (with padding mask) --------------------------
// grid = B*NH*LQ, block 256
__global__ void softmax_pq_kernel(const float* __restrict__ S, const float* __restrict__ pad_mask,
                                  float* __restrict__ P) {
    int gid = blockIdx.x;                // bh*LQ + q
    int bh = gid >> 8;
    int b = bh >> 3;
    const float* row = S + (size_t)gid * LK;
    int t = threadIdx.x;
    float v0 = row[t]       + (1.0f - pad_mask[b * LK + t])       * (-10000.0f);
    float v1 = row[t + 256] + (1.0f - pad_mask[b * LK + t + 256]) * (-10000.0f);
    float m = block_reduce_max(fmaxf(v0, v1));
    float e0 = expf(v0 - m), e1 = expf(v1 - m);
    float s = block_reduce_sum(e0 + e1);
    float inv = 1.0f / s;
    P[(size_t)gid * LK + t] = e0 * inv;
    P[(size_t)gid * LK + t + 256] = e1 * inv;
}

// ---------------- pv softmax over q, written as Pv[bh][k][q] ---------------------
// grid (LK/32, B*NH), block (32,8)
__global__ void softmax_pv_kernel(const float* __restrict__ S, const float* __restrict__ ext_mask,
                                  float* __restrict__ PT) {
    __shared__ float tile[256][33];
    __shared__ float red[8][32];
    __shared__ float colmax[32];
    __shared__ float colinv[32];
    int bh = blockIdx.y;
    int b = bh >> 3;
    int k0 = blockIdx.x * 32;
    int tx = threadIdx.x, ty = threadIdx.y;
    const float* Sp = S + (size_t)bh * LQ * LK;
    #pragma unroll 4
    for (int qq = 0; qq < 32; qq++) {
        int q = ty * 32 + qq;
        tile[q][tx] = Sp[(size_t)q * LK + k0 + tx] + ext_mask[b * LQ + q];
    }
    __syncthreads();
    float m = -INFINITY;
    #pragma unroll 4
    for (int qq = 0; qq < 32; qq++) m = fmaxf(m, tile[ty * 32 + qq][tx]);
    red[ty][tx] = m;
    __syncthreads();
    if (ty == 0) {
        float mm = red[0][tx];
        #pragma unroll
        for (int r = 1; r < 8; r++) mm = fmaxf(mm, red[r][tx]);
        colmax[tx] = mm;
    }
    __syncthreads();
    float cm = colmax[tx];
    float s = 0.0f;
    #pragma unroll 4
    for (int qq = 0; qq < 32; qq++) s += expf(tile[ty * 32 + qq][tx] - cm);
    red[ty][tx] = s;
    __syncthreads();
    if (ty == 0) {
        float ss = red[0][tx];
        #pragma unroll
        for (int r = 1; r < 8; r++) ss += red[r][tx];
        colinv[tx] = 1.0f / ss;
    }
    __syncthreads();
    int q = ty * 32 + tx;
    #pragma unroll 1
    for (int kl = 0; kl < 32; kl++) {
        float cmk = colmax[kl];
        float inv = colinv[kl];
        PT[((size_t)bh * LK + k0 + kl) * LQ + q] = expf(tile[q][kl] - cmk) * inv;
    }
}

// ---------------- query_out = LN(O + query) --------------------------------------
__global__ void ln_query_kernel(const float* __restrict__ O, const float* __restrict__ query,
                                const float* __restrict__ g, const float* __restrict__ bb,
                                float* __restrict__ out) {
    int row = blockIdx.x;
    int t = threadIdx.x;
    size_t i = (size_t)row * HH + t;
    float x = O[i] + query[i];
    float m = block_reduce_sum(x) * (1.0f / HH);
    float dx = x - m;
    float v = block_reduce_sum(dx * dx) * (1.0f / HH);
    out[i] = dx * rsqrtf(v + 1e-12f) * g[t] + bb[t];
}

// ---------------- value_new = LN(theta*vc + (1-theta)*vp) ------------------------
__global__ void gate_ln_kernel(const float* __restrict__ T1, const float* __restrict__ T2,
                               const float* __restrict__ VC, const float* __restrict__ VP,
                               const float* __restrict__ g, const float* __restrict__ bb,
                               float* __restrict__ vnew) {
    int row = blockIdx.x;
    int t = threadIdx.x;
    size_t i = (size_t)row * HH + t;
    float th = 1.0f / (1.0f + expf(-(T1[i] + T2[i])));
    float x = th * VC[i] + (1.0f - th) * VP[i];
    float m = block_reduce_sum(x) * (1.0f / HH);
    float dx = x - m;
    float v = block_reduce_sum(dx * dx) * (1.0f / HH);
    vnew[i] = dx * rsqrtf(v + 1e-12f) * g[t] + bb[t];
}

// ---------------- scatter mean ---------------------------------------------------
__global__ void scatter_sum_kernel(const float* __restrict__ vnew, const int* __restrict__ dst,
                                   const int* __restrict__ eb, const int* __restrict__ ep,
                                   float* __restrict__ sums, float* __restrict__ cnts) {
    int e = blockIdx.x;
    int t = threadIdx.x;
    int b = eb[e], p = ep[e], d = dst[e];
    atomicAdd(&sums[(size_t)d * HH + t], vnew[((size_t)b * LK + p) * HH + t]);
    if (t == 0) atomicAdd(&cnts[d], 1.0f);
}

__global__ void finalize_kernel(const float* __restrict__ sums, const float* __restrict__ cnts,
                                const float* __restrict__ graph, float* __restrict__ out) {
    size_t idx = (size_t)blockIdx.x * 256 + threadIdx.x;
    float c = cnts[idx >> 8];
    out[idx] = (c > 0.5f) ? sums[idx] / c : graph[idx];
}

// ---------------- host orchestration ---------------------------------------------
extern "C" void kernel_launch(void* const* d_in, const int* in_sizes, int n_in,
                              void* d_out, int out_size) {
    const float* ext   = (const float*)d_in[0];
    const float* query = (const float*)d_in[1];
    const float* rel   = (const float*)d_in[2];
    const float* graph = (const float*)d_in[3];
    const int*   src   = (const int*)d_in[4];
    const int*   dst   = (const int*)d_in[5];
    const int*   eb    = (const int*)d_in[6];
    const int*   ep    = (const int*)d_in[7];
    const float* pad   = (const float*)d_in[8];
    const float* Wq = (const float*)d_in[9];  const float* bq = (const float*)d_in[10];
    const float* Wk = (const float*)d_in[11]; const float* bk = (const float*)d_in[12];
    const float* Wv = (const float*)d_in[13]; const float* bv = (const float*)d_in[14];
    const float* Wo = (const float*)d_in[15]; const float* bo = (const float*)d_in[16];
    const float* l1g = (const float*)d_in[17]; const float* l1b = (const float*)d_in[18];
    const float* W1 = (const float*)d_in[19]; const float* b1 = (const float*)d_in[20];
    const float* W2 = (const float*)d_in[21]; const float* b2 = (const float*)d_in[22];
    const float* l2g = (const float*)d_in[23]; const float* l2b = (const float*)d_in[24];
    int E = in_sizes[4];
    float* out = (float*)d_out;

    float *kp, *vp, *Qb, *Kb, *Vb, *Sb, *Pq, *Pv, *qc, *vc, *Ob, *T1, *T2, *vn, *sums, *cnts;
    cudaGetSymbolAddress((void**)&kp, g_key_pad);
    cudaGetSymbolAddress((void**)&vp, g_val_pad);
    cudaGetSymbolAddress((void**)&Qb, g_Q);
    cudaGetSymbolAddress((void**)&Kb, g_K);
    cudaGetSymbolAddress((void**)&Vb, g_V);
    cudaGetSymbolAddress((void**)&Sb, g_scores);
    cudaGetSymbolAddress((void**)&Pq, g_pq);
    cudaGetSymbolAddress((void**)&Pv, g_pv);
    cudaGetSymbolAddress((void**)&qc, g_qctx);
    cudaGetSymbolAddress((void**)&vc, g_vctx);
    cudaGetSymbolAddress((void**)&Ob, g_O);
    cudaGetSymbolAddress((void**)&T1, g_T1);
    cudaGetSymbolAddress((void**)&T2, g_T2);
    cudaGetSymbolAddress((void**)&vn, g_vnew);
    cudaGetSymbolAddress((void**)&sums, g_sums);
    cudaGetSymbolAddress((void**)&cnts, g_cnts);

    // 1. zero pads + accumulators
    zero_kernel<<<2048, 256>>>(kp, (size_t)BB * LK * H2);
    zero_kernel<<<2048, 256>>>(vp, (size_t)BB * LK * HH);
    zero_kernel<<<1024, 256>>>(sums, (size_t)NN * HH);
    zero_kernel<<<32, 256>>>(cnts, (size_t)NN);

    // 2. scatter edges into padded K/V inputs
    scatter_edges_kernel<<<E, 256>>>(graph, rel, src, dst, eb, ep, kp, vp);

    // 3. projections (tf32 MMA)
    gemm_tf32_kernel<<<dim3(4, 64),  256>>>(query, Wq, bq, Qb, BB * LQ, HH, HH);
    gemm_tf32_kernel<<<dim3(4, 128), 256>>>(kp, Wk, bk, Kb, BB * LK, HH, H2);
    gemm_tf32_kernel<<<dim3(4, 128), 256>>>(vp, Wv, bv, Vb, BB * LK, HH, HH);

    // 4. attention scores (tf32 MMA, shared by both softmaxes)
    scores_tf32_kernel<<<dim3(8, 2, BB * NHD), 256>>>(Qb, Kb, Sb);

    // 5. softmaxes
    softmax_pq_kernel<<<BB * NHD * LQ, 256>>>(Sb, pad, Pq);
    softmax_pv_kernel<<<dim3(16, BB * NHD), dim3(32, 8)>>>(Sb, ext, Pv);

    // 6. contexts (tf32 MMA)
    ctx_tf32_kernel<<<dim3(2, BB * NHD), 256>>>(Pq, Vb, qc, LQ, LK);   // qctx
    ctx_tf32_kernel<<<dim3(4, BB * NHD), 256>>>(Pv, Qb, vc, LK, LQ);   // vctx

    // 7. output projection + LN (query_out -> second half of d_out)
    gemm_tf32_kernel<<<dim3(4, 64), 256>>>(qc, Wo, bo, Ob, BB * LQ, HH, HH);
    ln_query_kernel<<<BB * LQ, 256>>>(Ob, query, l1g, l1b, out + (size_t)NN * HH);

    // 8. gate + LN
    gemm_tf32_kernel<<<dim3(4, 128), 256>>>(vc, W1, b1, T1, BB * LK, HH, HH);
    gemm_tf32_kernel<<<dim3(4, 128), 256>>>(vp, W2, b2, T2, BB * LK, HH, HH);
    gate_ln_kernel<<<BB * LK, 256>>>(T1, T2, vc, vp, l2g, l2b, vn);

    // 9. scatter-mean memory update (graph_new -> first half of d_out)
    scatter_sum_kernel<<<E, 256>>>(vn, dst, eb, ep, sums, cnts);
    finalize_kernel<<<NN, 256>>>(sums, cnts, graph, out);
}